// round 16
// baseline (speedup 1.0000x reference)
#include <cuda_runtime.h>
#include <cuda_bf16.h>

#define WARPS_PER_BLOCK 8
#define NTHREADS (WARPS_PER_BLOCK * 32)
#define NDIR_MAX 800
#define BATCHES_PER_WARP 4

__device__ __forceinline__ float fex2(float x){ float r; asm("ex2.approx.f32 %0,%1;" : "=f"(r) : "f"(x)); return r; }
__device__ __forceinline__ float flg2(float x){ float r; asm("lg2.approx.f32 %0,%1;" : "=f"(r) : "f"(x)); return r; }
__device__ __forceinline__ float frcp(float x){ float r; asm("rcp.approx.f32 %0,%1;" : "=f"(r) : "f"(x)); return r; }

__global__ __launch_bounds__(NTHREADS, 4)
void closure_kernel(const float* __restrict__ F4,
                    const float* __restrict__ gdx,
                    const float* __restrict__ gdy,
                    const float* __restrict__ gdz,
                    const float* __restrict__ gqw,
                    float* __restrict__ out,
                    int B, int nd)
{
    // Quad symmetry (20 theta x 40 phi midpoint grid when nd==800):
    //   base (ti,pj), ti<10, pj<20; members share |x|,|y|,|z| and weight:
    //   m1=(x,y,z)  m2=(x,y,-z)  m3=(-x,-y,z)  m4=(-x,-y,-z)
    __shared__ float4 s_dir[NDIR_MAX];               // quads (x,y,z,log2 w) | raw dirs
    const bool paired = (nd == 800);
    if (paired) {
        for (int j = threadIdx.x; j < 200; j += NTHREADS) {
            int ti = j / 20, pj = j % 20;
            int d = ti * 40 + pj;
            s_dir[j] = make_float4(gdx[d], gdy[d], gdz[d], flg2(gqw[d]));
        }
    } else {
        for (int j = threadIdx.x; j < nd; j += NTHREADS)
            s_dir[j] = make_float4(gdx[j], gdy[j], gdz[j], flg2(gqw[j]));
    }
    __syncthreads();

    const int warp = threadIdx.x >> 5;
    const int lane = threadIdx.x & 31;
    const int hl   = lane & 7;                       // lane within 8-lane group
    int b = blockIdx.x * (WARPS_PER_BLOCK * BATCHES_PER_WARP)
          + warp * BATCHES_PER_WARP + (lane >> 3);
    bool active = (b < B);
    int bs = active ? b : 0;

    const float EPS    = 1e-12f;
    const float INV4PI = 0.07957747154594767f;
    const float LOG2E  = 1.4426950408889634f;

    const float4* in4 = (const float4*)(F4 + (size_t)bs * 24);
    float4 i0 = in4[0], i1 = in4[1], i2 = in4[2], i3 = in4[3], i4 = in4[4], i5 = in4[5];

    // species: 0=e, 1=ebar, 2=x, 3=xbar
    float Fx[4], Fy[4], Fz[4], Ns[4];
    Fx[0] = i0.x;  Fy[0] = i0.y;  Fz[0] = i0.z;  Ns[0] = i0.w;
    Fx[1] = i3.x;  Fy[1] = i3.y;  Fz[1] = i3.z;  Ns[1] = i3.w;
    Fx[2] = 0.5f*(i1.x + i2.x); Fy[2] = 0.5f*(i1.y + i2.y);
    Fz[2] = 0.5f*(i1.z + i2.z); Ns[2] = 0.5f*(i1.w + i2.w);
    Fx[3] = 0.5f*(i4.x + i5.x); Fy[3] = 0.5f*(i4.y + i5.y);
    Fz[3] = 0.5f*(i4.z + i5.z); Ns[3] = 0.5f*(i4.w + i5.w);

    float La[4], Kx[4], Ky[4], Kz[4];
    #pragma unroll
    for (int s = 0; s < 4; s++) {
        float N   = fmaxf(Ns[s], EPS);
        float ss  = Fx[s]*Fx[s] + Fy[s]*Fy[s] + Fz[s]*Fz[s];
        float rs  = rsqrtf(fmaxf(ss, 1e-30f));
        float nrm = ss * rs;
        float f   = fminf(fmaxf(nrm * frcp(N), 0.0f), 0.999999f);
        float f2 = f*f, f4 = f2*f2, f6 = f4*f2, f8 = f4*f4;
        float denom = 3.0f - 1.00651f*f2 - 0.962251f*f4 + 1.47353f*f6 - 0.48953f*f8;
        float p = 1.0f - 2.0f*(1.0f - f)*(1.0f + 1.01524f*f) * frcp(fmaxf(denom, EPS));
        float Z = 2.0f*f * frcp(fmaxf(1.0f - p, 1e-6f));
        Z = fminf(Z, 85.0f);
        float zsz;
        if (fabsf(Z) < 1e-4f) {
            float z2 = Z*Z;
            zsz = 1.0f - z2*(1.0f/6.0f) + z2*z2*(1.0f/120.0f);
        } else {
            float E  = fex2(Z * LOG2E);
            float Em = fex2(-Z * LOG2E);
            zsz = Z * frcp(0.5f * (E - Em));
        }
        float A = N * INV4PI * zsz;
        La[s] = flg2(A);
        float scl = Z * LOG2E * rs;
        Kx[s] = Fx[s]*scl; Ky[s] = Fy[s]*scl; Kz[s] = Fz[s]*scl;
    }

    float acc[24];
    #pragma unroll
    for (int i = 0; i < 24; i++) acc[i] = 0.0f;

    // per-species quad step: 4 member exps + paired moment accumulation.
    // g1=(x,y,z) g2=(x,y,-z) g3=(-x,-y,z) g4=(-x,-y,-z)
    #define SPECIES_QUAD(s, ST1, ST2, ST3, ST4)                              \
    {                                                                        \
        float a  = fmaf(Ky[s], qy, Kx[s]*qx);                                \
        float cz = Kz[s]*qz;                                                 \
        float c0 = La[s] + lw;                                               \
        float P = c0 + a, M = c0 - a;                                        \
        float g1 = fex2(P + cz);                                             \
        float g2 = fex2(P - cz);                                             \
        float g3 = fex2(M + cz);                                             \
        float g4 = fex2(M - cz);                                             \
        float s12 = g1 + g2, s34 = g3 + g4;                                  \
        acc[4*(s)+0] += s12 + s34;                                           \
        float dxy = s12 - s34;                                               \
        acc[4*(s)+1] = fmaf(dxy, qx, acc[4*(s)+1]);                          \
        acc[4*(s)+2] = fmaf(dxy, qy, acc[4*(s)+2]);                          \
        float dz = (g1 - g2) + (g3 - g4);                                    \
        acc[4*(s)+3] = fmaf(dz, qz, acc[4*(s)+3]);                           \
        ST1; ST2; ST3; ST4;                                                  \
    }

    if (paired) {
        #pragma unroll 5
        for (int qi = hl; qi < 200; qi += 8) {
            float4 q = s_dir[qi];
            float qx = q.x, qy = q.y, qz = q.z, lw = q.w;
            float u4[4], h4[4];
            SPECIES_QUAD(0, u4[0] = g1, u4[1] = g2, u4[2] = g3, u4[3] = g4)  // e
            SPECIES_QUAD(2, u4[0] -= g1, u4[1] -= g2, u4[2] -= g3, u4[3] -= g4) // x -> u
            SPECIES_QUAD(1, h4[0] = g1, h4[1] = g2, h4[2] = g3, h4[3] = g4)  // ebar
            SPECIES_QUAD(3, h4[0] -= g1, h4[1] -= g2, h4[2] -= g3, h4[3] -= g4) // xbar -> v
            // positive-delta buckets per member (signs per member direction)
            if (u4[0] >= h4[0]) {   // (+x,+y,+z)
                acc[16] += u4[0]; acc[17] = fmaf(u4[0],  qx, acc[17]); acc[18] = fmaf(u4[0],  qy, acc[18]); acc[19] = fmaf(u4[0],  qz, acc[19]);
                acc[20] += h4[0]; acc[21] = fmaf(h4[0],  qx, acc[21]); acc[22] = fmaf(h4[0],  qy, acc[22]); acc[23] = fmaf(h4[0],  qz, acc[23]);
            }
            if (u4[1] >= h4[1]) {   // (+x,+y,-z)
                acc[16] += u4[1]; acc[17] = fmaf(u4[1],  qx, acc[17]); acc[18] = fmaf(u4[1],  qy, acc[18]); acc[19] = fmaf(u4[1], -qz, acc[19]);
                acc[20] += h4[1]; acc[21] = fmaf(h4[1],  qx, acc[21]); acc[22] = fmaf(h4[1],  qy, acc[22]); acc[23] = fmaf(h4[1], -qz, acc[23]);
            }
            if (u4[2] >= h4[2]) {   // (-x,-y,+z)
                acc[16] += u4[2]; acc[17] = fmaf(u4[2], -qx, acc[17]); acc[18] = fmaf(u4[2], -qy, acc[18]); acc[19] = fmaf(u4[2],  qz, acc[19]);
                acc[20] += h4[2]; acc[21] = fmaf(h4[2], -qx, acc[21]); acc[22] = fmaf(h4[2], -qy, acc[22]); acc[23] = fmaf(h4[2],  qz, acc[23]);
            }
            if (u4[3] >= h4[3]) {   // (-x,-y,-z)
                acc[16] += u4[3]; acc[17] = fmaf(u4[3], -qx, acc[17]); acc[18] = fmaf(u4[3], -qy, acc[18]); acc[19] = fmaf(u4[3], -qz, acc[19]);
                acc[20] += h4[3]; acc[21] = fmaf(h4[3], -qx, acc[21]); acc[22] = fmaf(h4[3], -qy, acc[22]); acc[23] = fmaf(h4[3], -qz, acc[23]);
            }
        }
    } else {
        for (int d = hl; d < nd; d += 8) {
            float4 q = s_dir[d];
            float lw = q.w;
            float g[4];
            #pragma unroll
            for (int s = 0; s < 4; s++) {
                float t = fmaf(Kx[s], q.x, fmaf(Ky[s], q.y, Kz[s]*q.z));
                g[s] = fex2(t + La[s] + lw);
                acc[4*s+0] += g[s];
                acc[4*s+1] = fmaf(g[s], q.x, acc[4*s+1]);
                acc[4*s+2] = fmaf(g[s], q.y, acc[4*s+2]);
                acc[4*s+3] = fmaf(g[s], q.z, acc[4*s+3]);
            }
            float wu = g[0] - g[2], wv = g[1] - g[3];
            if (wu >= wv) {
                acc[16] += wu; acc[17] = fmaf(wu, q.x, acc[17]); acc[18] = fmaf(wu, q.y, acc[18]); acc[19] = fmaf(wu, q.z, acc[19]);
                acc[20] += wv; acc[21] = fmaf(wv, q.x, acc[21]); acc[22] = fmaf(wv, q.y, acc[22]); acc[23] = fmaf(wv, q.z, acc[23]);
            }
        }
    }

    // 8-wide butterfly reduction within each 8-lane group
    #pragma unroll
    for (int off = 4; off > 0; off >>= 1) {
        #pragma unroll
        for (int i = 0; i < 24; i++)
            acc[i] += __shfl_xor_sync(0xffffffffu, acc[i], off);
    }

    float Su[4], Sv[4];
    #pragma unroll
    for (int k = 0; k < 4; k++) {
        Su[k] = acc[0 + k] - acc[8 + k];
        Sv[k] = acc[4 + k] - acc[12 + k];
    }
    float Iplus  = acc[16] - acc[20];
    float Iminus = (Sv[0] - acc[20]) - (Su[0] - acc[16]);
    float Ips = fmaxf(Iplus,  EPS);
    float Ims = fmaxf(Iminus, EPS);
    float cp, cn;
    if (Iplus < Iminus) {
        cp = 1.0f / 3.0f;
        cn = fminf(fmaxf(1.0f - (2.0f/3.0f)*(Ips/Ims), 0.0f), 1.0f);
    } else {
        cn = 1.0f / 3.0f;
        cp = fminf(fmaxf(1.0f - (2.0f/3.0f)*(Ims/Ips), 0.0f), 1.0f);
    }
    float growth = sqrtf(fmaxf(Iplus * Iminus, 0.0f));

    float n0[4], n1[4], n2[4], n3[4];
    #pragma unroll
    for (int k = 0; k < 4; k++) {
        float Pu = cp*acc[16 + k] + cn*(Su[k] - acc[16 + k]);
        float Pv = cp*acc[20 + k] + cn*(Sv[k] - acc[20 + k]);
        n0[k] = acc[8 + k]  + Pu;
        n1[k] = acc[12 + k] + Pv;
        n2[k] = 0.5f*(acc[0 + k] + acc[8 + k])  - 0.5f*Pu;
        n3[k] = 0.5f*(acc[4 + k] + acc[12 + k]) - 0.5f*Pv;
    }

    // F4mix layout (B,2,3,4): channel order [Fx,Fy,Fz,N]
    if (active) {
        float4* ob = (float4*)(out + (size_t)b * 24);
        if (hl == 0) ob[0] = make_float4(n0[1], n0[2], n0[3], n0[0]); // i=0,f=0 (e)
        if (hl == 1) ob[1] = make_float4(n2[1], n2[2], n2[3], n2[0]); // i=0,f=1 (x)
        if (hl == 2) ob[2] = make_float4(n2[1], n2[2], n2[3], n2[0]); // i=0,f=2 (x)
        if (hl == 3) ob[3] = make_float4(n1[1], n1[2], n1[3], n1[0]); // i=1,f=0 (ebar)
        if (hl == 4) ob[4] = make_float4(n3[1], n3[2], n3[3], n3[0]); // i=1,f=1 (xbar)
        if (hl == 5) ob[5] = make_float4(n3[1], n3[2], n3[3], n3[0]); // i=1,f=2 (xbar)
        if (hl == 6) out[(size_t)B * 24 + b] = growth;
    }
}

extern "C" void kernel_launch(void* const* d_in, const int* in_sizes, int n_in,
                              void* d_out, int out_size) {
    const float* F4  = (const float*)d_in[0];
    const float* ddx = (const float*)d_in[1];
    const float* ddy = (const float*)d_in[2];
    const float* ddz = (const float*)d_in[3];
    const float* dqw = (const float*)d_in[4];
    float* out = (float*)d_out;

    int B  = in_sizes[0] / 24;
    int nd = in_sizes[1];

    const int batches_per_block = WARPS_PER_BLOCK * BATCHES_PER_WARP;
    int grid = (B + batches_per_block - 1) / batches_per_block;
    closure_kernel<<<grid, NTHREADS>>>(F4, ddx, ddy, ddz, dqw, out, B, nd);
}

// round 17
// speedup vs baseline: 1.0054x; 1.0054x over previous
#include <cuda_runtime.h>
#include <cuda_bf16.h>

#define WARPS_PER_BLOCK 8
#define NTHREADS (WARPS_PER_BLOCK * 32)
#define NDIR_MAX 800
#define BATCHES_PER_WARP 4

__device__ __forceinline__ float fex2(float x){ float r; asm("ex2.approx.f32 %0,%1;" : "=f"(r) : "f"(x)); return r; }
__device__ __forceinline__ float flg2(float x){ float r; asm("lg2.approx.f32 %0,%1;" : "=f"(r) : "f"(x)); return r; }
__device__ __forceinline__ float frcp(float x){ float r; asm("rcp.approx.f32 %0,%1;" : "=f"(r) : "f"(x)); return r; }

__global__ __launch_bounds__(NTHREADS, 4)
void closure_kernel(const float* __restrict__ F4,
                    const float* __restrict__ gdx,
                    const float* __restrict__ gdy,
                    const float* __restrict__ gdz,
                    const float* __restrict__ gqw,
                    float* __restrict__ out,
                    int B, int nd)
{
    // Quad symmetry (20 theta x 40 phi midpoint grid when nd==800):
    //   base (ti,pj), ti<10, pj<20; members share |x|,|y|,|z| and weight:
    //   m1=(x,y,z)  m2=(x,y,-z)  m3=(-x,-y,z)  m4=(-x,-y,-z)
    __shared__ float4 s_dir[NDIR_MAX];               // quads (x,y,z,log2 w) | raw dirs
    const bool paired = (nd == 800);
    if (paired) {
        for (int j = threadIdx.x; j < 200; j += NTHREADS) {
            int ti = j / 20, pj = j % 20;
            int d = ti * 40 + pj;
            s_dir[j] = make_float4(gdx[d], gdy[d], gdz[d], flg2(gqw[d]));
        }
    } else {
        for (int j = threadIdx.x; j < nd; j += NTHREADS)
            s_dir[j] = make_float4(gdx[j], gdy[j], gdz[j], flg2(gqw[j]));
    }
    __syncthreads();

    const int warp = threadIdx.x >> 5;
    const int lane = threadIdx.x & 31;
    const int hl   = lane & 7;                       // lane within 8-lane group
    int b = blockIdx.x * (WARPS_PER_BLOCK * BATCHES_PER_WARP)
          + warp * BATCHES_PER_WARP + (lane >> 3);
    bool active = (b < B);
    int bs = active ? b : 0;

    const float EPS    = 1e-12f;
    const float INV4PI = 0.07957747154594767f;
    const float LOG2E  = 1.4426950408889634f;

    const float4* in4 = (const float4*)(F4 + (size_t)bs * 24);
    float4 i0 = in4[0], i1 = in4[1], i2 = in4[2], i3 = in4[3], i4 = in4[4], i5 = in4[5];

    // species: 0=e, 1=ebar, 2=x, 3=xbar
    float Fx[4], Fy[4], Fz[4], Ns[4];
    Fx[0] = i0.x;  Fy[0] = i0.y;  Fz[0] = i0.z;  Ns[0] = i0.w;
    Fx[1] = i3.x;  Fy[1] = i3.y;  Fz[1] = i3.z;  Ns[1] = i3.w;
    Fx[2] = 0.5f*(i1.x + i2.x); Fy[2] = 0.5f*(i1.y + i2.y);
    Fz[2] = 0.5f*(i1.z + i2.z); Ns[2] = 0.5f*(i1.w + i2.w);
    Fx[3] = 0.5f*(i4.x + i5.x); Fy[3] = 0.5f*(i4.y + i5.y);
    Fz[3] = 0.5f*(i4.z + i5.z); Ns[3] = 0.5f*(i4.w + i5.w);

    float La[4], Kx[4], Ky[4], Kz[4];
    #pragma unroll
    for (int s = 0; s < 4; s++) {
        float N   = fmaxf(Ns[s], EPS);
        float ss  = Fx[s]*Fx[s] + Fy[s]*Fy[s] + Fz[s]*Fz[s];
        float rs  = rsqrtf(fmaxf(ss, 1e-30f));
        float nrm = ss * rs;
        float f   = fminf(fmaxf(nrm * frcp(N), 0.0f), 0.999999f);
        float f2 = f*f, f4 = f2*f2, f6 = f4*f2, f8 = f4*f4;
        float denom = 3.0f - 1.00651f*f2 - 0.962251f*f4 + 1.47353f*f6 - 0.48953f*f8;
        float p = 1.0f - 2.0f*(1.0f - f)*(1.0f + 1.01524f*f) * frcp(fmaxf(denom, EPS));
        float Z = 2.0f*f * frcp(fmaxf(1.0f - p, 1e-6f));
        Z = fminf(Z, 85.0f);
        float zsz;
        if (fabsf(Z) < 1e-4f) {
            float z2 = Z*Z;
            zsz = 1.0f - z2*(1.0f/6.0f) + z2*z2*(1.0f/120.0f);
        } else {
            float E  = fex2(Z * LOG2E);
            float Em = fex2(-Z * LOG2E);
            zsz = Z * frcp(0.5f * (E - Em));
        }
        float A = N * INV4PI * zsz;
        La[s] = flg2(A);
        float scl = Z * LOG2E * rs;
        Kx[s] = Fx[s]*scl; Ky[s] = Fy[s]*scl; Kz[s] = Fz[s]*scl;
    }

    float acc[24];
    #pragma unroll
    for (int i = 0; i < 24; i++) acc[i] = 0.0f;

    // per-species quad step: 4 member exps + paired moment accumulation.
    // g1=(x,y,z) g2=(x,y,-z) g3=(-x,-y,z) g4=(-x,-y,-z)
    #define SPECIES_QUAD(s, ST1, ST2, ST3, ST4)                              \
    {                                                                        \
        float a  = fmaf(Ky[s], qy, Kx[s]*qx);                                \
        float cz = Kz[s]*qz;                                                 \
        float c0 = La[s] + lw;                                               \
        float P = c0 + a, M = c0 - a;                                        \
        float g1 = fex2(P + cz);                                             \
        float g2 = fex2(P - cz);                                             \
        float g3 = fex2(M + cz);                                             \
        float g4 = fex2(M - cz);                                             \
        float s12 = g1 + g2, s34 = g3 + g4;                                  \
        acc[4*(s)+0] += s12 + s34;                                           \
        float dxy = s12 - s34;                                               \
        acc[4*(s)+1] = fmaf(dxy, qx, acc[4*(s)+1]);                          \
        acc[4*(s)+2] = fmaf(dxy, qy, acc[4*(s)+2]);                          \
        float dz = (g1 - g2) + (g3 - g4);                                    \
        acc[4*(s)+3] = fmaf(dz, qz, acc[4*(s)+3]);                           \
        ST1; ST2; ST3; ST4;                                                  \
    }

    if (paired) {
        #pragma unroll 5
        for (int qi = hl; qi < 200; qi += 8) {
            float4 q = s_dir[qi];
            float qx = q.x, qy = q.y, qz = q.z, lw = q.w;
            float u4[4], h4[4];
            SPECIES_QUAD(0, u4[0] = g1, u4[1] = g2, u4[2] = g3, u4[3] = g4)  // e
            SPECIES_QUAD(2, u4[0] -= g1, u4[1] -= g2, u4[2] -= g3, u4[3] -= g4) // x -> u
            SPECIES_QUAD(1, h4[0] = g1, h4[1] = g2, h4[2] = g3, h4[3] = g4)  // ebar
            SPECIES_QUAD(3, h4[0] -= g1, h4[1] -= g2, h4[2] -= g3, h4[3] -= g4) // xbar -> v
            // positive-delta buckets: predicate each member, then fold the 4
            // members' moments via sign-pattern sums/differences.
            bool c1 = (u4[0] >= h4[0]);
            bool c2 = (u4[1] >= h4[1]);
            bool c3 = (u4[2] >= h4[2]);
            bool c4 = (u4[3] >= h4[3]);
            float ua = c1 ? u4[0] : 0.0f, va = c1 ? h4[0] : 0.0f;
            float ub = c2 ? u4[1] : 0.0f, vb = c2 ? h4[1] : 0.0f;
            float uc = c3 ? u4[2] : 0.0f, vc = c3 ? h4[2] : 0.0f;
            float ud = c4 ? u4[3] : 0.0f, vd = c4 ? h4[3] : 0.0f;
            {   // u moments: m1(+,+,+) m2(+,+,-) m3(-,-,+) m4(-,-,-)
                float t1 = ua + ub, t2 = uc + ud;
                acc[16] += t1 + t2;
                float dxy = t1 - t2;
                acc[17] = fmaf(dxy, qx, acc[17]);
                acc[18] = fmaf(dxy, qy, acc[18]);
                float dz = (ua - ub) + (uc - ud);
                acc[19] = fmaf(dz, qz, acc[19]);
            }
            {   // v moments
                float t1 = va + vb, t2 = vc + vd;
                acc[20] += t1 + t2;
                float dxy = t1 - t2;
                acc[21] = fmaf(dxy, qx, acc[21]);
                acc[22] = fmaf(dxy, qy, acc[22]);
                float dz = (va - vb) + (vc - vd);
                acc[23] = fmaf(dz, qz, acc[23]);
            }
        }
    } else {
        for (int d = hl; d < nd; d += 8) {
            float4 q = s_dir[d];
            float lw = q.w;
            float g[4];
            #pragma unroll
            for (int s = 0; s < 4; s++) {
                float t = fmaf(Kx[s], q.x, fmaf(Ky[s], q.y, Kz[s]*q.z));
                g[s] = fex2(t + La[s] + lw);
                acc[4*s+0] += g[s];
                acc[4*s+1] = fmaf(g[s], q.x, acc[4*s+1]);
                acc[4*s+2] = fmaf(g[s], q.y, acc[4*s+2]);
                acc[4*s+3] = fmaf(g[s], q.z, acc[4*s+3]);
            }
            float wu = g[0] - g[2], wv = g[1] - g[3];
            if (wu >= wv) {
                acc[16] += wu; acc[17] = fmaf(wu, q.x, acc[17]); acc[18] = fmaf(wu, q.y, acc[18]); acc[19] = fmaf(wu, q.z, acc[19]);
                acc[20] += wv; acc[21] = fmaf(wv, q.x, acc[21]); acc[22] = fmaf(wv, q.y, acc[22]); acc[23] = fmaf(wv, q.z, acc[23]);
            }
        }
    }

    // 8-wide butterfly reduction within each 8-lane group
    #pragma unroll
    for (int off = 4; off > 0; off >>= 1) {
        #pragma unroll
        for (int i = 0; i < 24; i++)
            acc[i] += __shfl_xor_sync(0xffffffffu, acc[i], off);
    }

    float Su[4], Sv[4];
    #pragma unroll
    for (int k = 0; k < 4; k++) {
        Su[k] = acc[0 + k] - acc[8 + k];
        Sv[k] = acc[4 + k] - acc[12 + k];
    }
    float Iplus  = acc[16] - acc[20];
    float Iminus = (Sv[0] - acc[20]) - (Su[0] - acc[16]);
    float Ips = fmaxf(Iplus,  EPS);
    float Ims = fmaxf(Iminus, EPS);
    float cp, cn;
    if (Iplus < Iminus) {
        cp = 1.0f / 3.0f;
        cn = fminf(fmaxf(1.0f - (2.0f/3.0f)*(Ips/Ims), 0.0f), 1.0f);
    } else {
        cn = 1.0f / 3.0f;
        cp = fminf(fmaxf(1.0f - (2.0f/3.0f)*(Ims/Ips), 0.0f), 1.0f);
    }
    float growth = sqrtf(fmaxf(Iplus * Iminus, 0.0f));

    float n0[4], n1[4], n2[4], n3[4];
    #pragma unroll
    for (int k = 0; k < 4; k++) {
        float Pu = cp*acc[16 + k] + cn*(Su[k] - acc[16 + k]);
        float Pv = cp*acc[20 + k] + cn*(Sv[k] - acc[20 + k]);
        n0[k] = acc[8 + k]  + Pu;
        n1[k] = acc[12 + k] + Pv;
        n2[k] = 0.5f*(acc[0 + k] + acc[8 + k])  - 0.5f*Pu;
        n3[k] = 0.5f*(acc[4 + k] + acc[12 + k]) - 0.5f*Pv;
    }

    // F4mix layout (B,2,3,4): channel order [Fx,Fy,Fz,N]
    if (active) {
        float4* ob = (float4*)(out + (size_t)b * 24);
        if (hl == 0) ob[0] = make_float4(n0[1], n0[2], n0[3], n0[0]); // i=0,f=0 (e)
        if (hl == 1) ob[1] = make_float4(n2[1], n2[2], n2[3], n2[0]); // i=0,f=1 (x)
        if (hl == 2) ob[2] = make_float4(n2[1], n2[2], n2[3], n2[0]); // i=0,f=2 (x)
        if (hl == 3) ob[3] = make_float4(n1[1], n1[2], n1[3], n1[0]); // i=1,f=0 (ebar)
        if (hl == 4) ob[4] = make_float4(n3[1], n3[2], n3[3], n3[0]); // i=1,f=1 (xbar)
        if (hl == 5) ob[5] = make_float4(n3[1], n3[2], n3[3], n3[0]); // i=1,f=2 (xbar)
        if (hl == 6) out[(size_t)B * 24 + b] = growth;
    }
}

extern "C" void kernel_launch(void* const* d_in, const int* in_sizes, int n_in,
                              void* d_out, int out_size) {
    const float* F4  = (const float*)d_in[0];
    const float* ddx = (const float*)d_in[1];
    const float* ddy = (const float*)d_in[2];
    const float* ddz = (const float*)d_in[3];
    const float* dqw = (const float*)d_in[4];
    float* out = (float*)d_out;

    int B  = in_sizes[0] / 24;
    int nd = in_sizes[1];

    const int batches_per_block = WARPS_PER_BLOCK * BATCHES_PER_WARP;
    int grid = (B + batches_per_block - 1) / batches_per_block;
    closure_kernel<<<grid, NTHREADS>>>(F4, ddx, ddy, ddz, dqw, out, B, nd);
}